// round 6
// baseline (speedup 1.0000x reference)
#include <cuda_runtime.h>
#include <cuda_bf16.h>
#include <cstdint>
#include <cstddef>

#define BATCH 1024
#define DIM   1024
#define HID   4096
#define TSTEPS 16
#define BD (BATCH*DIM)

__device__ __nv_bfloat16 g_W1h[(size_t)HID * DIM];
__device__ __nv_bfloat16 g_W1l[(size_t)HID * DIM];
__device__ __nv_bfloat16 g_W2h[(size_t)DIM * HID];
__device__ __nv_bfloat16 g_W2l[(size_t)DIM * HID];
__device__ __nv_bfloat16 g_Hh[(size_t)BATCH * HID];
__device__ __nv_bfloat16 g_Hl[(size_t)BATCH * HID];
__device__ __nv_bfloat16 g_Yh[BD];
__device__ __nv_bfloat16 g_Yl[BD];
__device__ float         g_Yacc[BD];

__device__ __forceinline__ uint32_t smem_u32(const void* p) {
    uint32_t a;
    asm("{ .reg .u64 t; cvta.to.shared.u64 t, %1; cvt.u32.u64 %0, t; }" : "=r"(a) : "l"(p));
    return a;
}
__device__ __forceinline__ void cpa16(uint32_t s, const void* g) {
    asm volatile("cp.async.cg.shared.global [%0], [%1], 16;"
                 :: "r"(s), "l"(__cvta_generic_to_global(g)));
}
#define CP_COMMIT() asm volatile("cp.async.commit_group;" ::: "memory")
#define CP_WAIT0()  asm volatile("cp.async.wait_group 0;" ::: "memory")

__device__ __forceinline__ void ldsm4(uint32_t* r, uint32_t addr) {
    asm volatile("ldmatrix.sync.aligned.m8n8.x4.shared.b16 {%0,%1,%2,%3}, [%4];"
                 : "=r"(r[0]), "=r"(r[1]), "=r"(r[2]), "=r"(r[3]) : "r"(addr));
}
__device__ __forceinline__ void mma_bf16(float* d, const uint32_t* a, const uint32_t* b) {
    asm volatile(
        "mma.sync.aligned.m16n8k16.row.col.f32.bf16.bf16.f32 "
        "{%0,%1,%2,%3}, {%4,%5,%6,%7}, {%8,%9}, {%0,%1,%2,%3};"
        : "+f"(d[0]), "+f"(d[1]), "+f"(d[2]), "+f"(d[3])
        : "r"(a[0]), "r"(a[1]), "r"(a[2]), "r"(a[3]), "r"(b[0]), "r"(b[1]));
}

__device__ __forceinline__ uint32_t split_pack(float a0, float a1, uint32_t& lo) {
    __nv_bfloat16 h0 = __float2bfloat16(a0);
    __nv_bfloat16 h1 = __float2bfloat16(a1);
    __nv_bfloat16 l0 = __float2bfloat16(a0 - __bfloat162float(h0));
    __nv_bfloat16 l1 = __float2bfloat16(a1 - __bfloat162float(h1));
    lo = ((uint32_t)__bfloat16_as_ushort(l1) << 16) | __bfloat16_as_ushort(l0);
    return ((uint32_t)__bfloat16_as_ushort(h1) << 16) | __bfloat16_as_ushort(h0);
}

// C tile [BM x 128] of A[M,K] @ B[N,K]^T via mma.sync bf16, split hi/lo 3-term.
// 256 threads, 8 warps as 2(M) x 4(N); warp tile = (BM/2) x 32; MI = BM/32.
// 1 CTA/SM, double-buffered BK=64 stages.
// EPI 0: O = tanh(acc+bias) -> Oh/Ol
// EPI 1: k=acc+bias; o=Yin+h/2*k; Yacc=Yin+h/6*k;  o->Oh/Ol
// EPI 2: k=acc+bias; o=Yin+h/2*k; Yacc+=h/3*k;     o->Oh/Ol
// EPI 3: k=acc+bias; o=Yin+h*k;   Yacc+=h/3*k;     o->Oh/Ol
// EPI 4: k=acc+bias; o=Yacc+h/6*k; o->Yout(f32) and Oh/Ol
template <int BM, int EPI>
__global__ void __launch_bounds__(256, 1)
hmma_gemm(const __nv_bfloat16* __restrict__ Ah, const __nv_bfloat16* __restrict__ Al,
          const __nv_bfloat16* __restrict__ Bh, const __nv_bfloat16* __restrict__ Bl,
          const float* __restrict__ bias, int K, int ldc,
          __nv_bfloat16* __restrict__ Oh, __nv_bfloat16* __restrict__ Ol,
          const float* __restrict__ Yin, float* __restrict__ Yacc,
          float* __restrict__ Yout, const float* __restrict__ tspan, int step) {
    constexpr int BN = 128;
    constexpr int MI = BM / 32;          // m16 fragments per warp
    constexpr int NT = 4;                // n8 fragments per warp (warp covers 32 cols)
    constexpr int APLANE = BM * 128;     // bytes per plane: BM rows x 128B (BK=64 bf16)
    constexpr int BPLANE = BN * 128;
    constexpr int STAGE = 2 * APLANE + 2 * BPLANE;
    extern __shared__ char smem[];
    const uint32_t sb0 = smem_u32(smem);

    const int tid = threadIdx.x;
    const int wid = tid >> 5, lane = tid & 31;
    const int wm = wid & 1, wn = wid >> 1;
    const int gid = lane >> 2, tig = lane & 3;
    const int rowBase = blockIdx.y * BM;
    const int colBase = blockIdx.x * BN;
    const int NC = K >> 6;

    auto load_stage = [&](int kc, int st) {
        const uint32_t sb = sb0 + st * STAGE;
        const size_t keB = (size_t)kc * 128;  // byte offset along K
#pragma unroll
        for (int c = tid; c < BM * 8; c += 256) {
            const int row = c >> 3, kb = (c & 7) << 4;
            const uint32_t so = row * 128 + (kb ^ ((row & 7) << 4));
            const size_t g = (size_t)(rowBase + row) * (K * 2) + keB + kb;
            cpa16(sb + so, (const char*)Ah + g);
            cpa16(sb + APLANE + so, (const char*)Al + g);
        }
#pragma unroll
        for (int c = tid; c < BN * 8; c += 256) {
            const int row = c >> 3, kb = (c & 7) << 4;
            const uint32_t so = row * 128 + (kb ^ ((row & 7) << 4));
            const size_t g = (size_t)(colBase + row) * (K * 2) + keB + kb;
            cpa16(sb + 2 * APLANE + so, (const char*)Bh + g);
            cpa16(sb + 2 * APLANE + BPLANE + so, (const char*)Bl + g);
        }
    };

    float acc[MI][NT][4];
#pragma unroll
    for (int i = 0; i < MI; ++i)
#pragma unroll
        for (int j = 0; j < NT; ++j)
#pragma unroll
            for (int e = 0; e < 4; ++e) acc[i][j][e] = 0.f;

    load_stage(0, 0);
    CP_COMMIT();

    for (int kc = 0; kc < NC; ++kc) {
        CP_WAIT0();
        __syncthreads();
        if (kc + 1 < NC) { load_stage(kc + 1, (kc + 1) & 1); CP_COMMIT(); }
        const uint32_t sb = sb0 + (kc & 1) * STAGE;
#pragma unroll
        for (int t = 0; t < 4; ++t) {  // four k16 slices per BK=64 chunk
            uint32_t af[2][MI][4];     // [plane hi/lo][mi][4 regs]
#pragma unroll
            for (int mi = 0; mi < MI; ++mi) {
                const int arow = wm * (16 * MI) + mi * 16 + (lane & 15);
                const int kb = t * 32 + ((lane >> 4) << 4);
                const uint32_t so = arow * 128 + (kb ^ ((arow & 7) << 4));
                ldsm4(af[0][mi], sb + so);
                ldsm4(af[1][mi], sb + APLANE + so);
            }
            uint32_t bfh[NT * 2], bfl[NT * 2];
#pragma unroll
            for (int bi = 0; bi < NT / 2; ++bi) {
                const int brow = wn * 32 + bi * 16 + ((lane >> 4) << 3) + (lane & 7);
                const int kb = t * 32 + (((lane >> 3) & 1) << 4);
                const uint32_t so = brow * 128 + (kb ^ ((brow & 7) << 4));
                ldsm4(&bfh[bi * 4], sb + 2 * APLANE + so);
                ldsm4(&bfl[bi * 4], sb + 2 * APLANE + BPLANE + so);
            }
#pragma unroll
            for (int mi = 0; mi < MI; ++mi)
#pragma unroll
                for (int ni = 0; ni < NT; ++ni) {
                    mma_bf16(acc[mi][ni], af[0][mi], &bfh[ni * 2]);
                    mma_bf16(acc[mi][ni], af[0][mi], &bfl[ni * 2]);
                    mma_bf16(acc[mi][ni], af[1][mi], &bfh[ni * 2]);
                }
        }
    }

    float h = 0.f;
    if (EPI >= 1) h = tspan[step + 1] - tspan[step];

    auto emit = [&](int row, int col, float v0, float v1) {
        const float2 bb = *reinterpret_cast<const float2*>(bias + col);
        v0 += bb.x;
        v1 += bb.y;
        const size_t ix = (size_t)row * ldc + col;
        float o0, o1;
        if (EPI == 0) {
            o0 = tanhf(v0);
            o1 = tanhf(v1);
        } else if (EPI == 1) {
            const float2 yy = *reinterpret_cast<const float2*>(Yin + ix);
            o0 = fmaf(0.5f * h, v0, yy.x);
            o1 = fmaf(0.5f * h, v1, yy.y);
            float2 aa;
            aa.x = fmaf(h * (1.f / 6.f), v0, yy.x);
            aa.y = fmaf(h * (1.f / 6.f), v1, yy.y);
            *reinterpret_cast<float2*>(Yacc + ix) = aa;
        } else if (EPI == 2 || EPI == 3) {
            const float cy = (EPI == 2) ? 0.5f : 1.0f;
            const float2 yy = *reinterpret_cast<const float2*>(Yin + ix);
            float2 aa = *reinterpret_cast<float2*>(Yacc + ix);
            o0 = fmaf(cy * h, v0, yy.x);
            o1 = fmaf(cy * h, v1, yy.y);
            aa.x = fmaf(h * (1.f / 3.f), v0, aa.x);
            aa.y = fmaf(h * (1.f / 3.f), v1, aa.y);
            *reinterpret_cast<float2*>(Yacc + ix) = aa;
        } else {
            const float2 aa = *reinterpret_cast<const float2*>(Yacc + ix);
            o0 = fmaf(h * (1.f / 6.f), v0, aa.x);
            o1 = fmaf(h * (1.f / 6.f), v1, aa.y);
            float2 oo;
            oo.x = o0;
            oo.y = o1;
            *reinterpret_cast<float2*>(Yout + ix) = oo;
        }
        uint32_t lo;
        const uint32_t hi = split_pack(o0, o1, lo);
        *reinterpret_cast<uint32_t*>(Oh + ix) = hi;
        *reinterpret_cast<uint32_t*>(Ol + ix) = lo;
    };

#pragma unroll
    for (int mi = 0; mi < MI; ++mi) {
        const int row = rowBase + wm * (16 * MI) + mi * 16 + gid;
#pragma unroll
        for (int ni = 0; ni < NT; ++ni) {
            const int col = colBase + wn * 32 + ni * 8 + tig * 2;
            emit(row, col, acc[mi][ni][0], acc[mi][ni][1]);
            emit(row + 8, col, acc[mi][ni][2], acc[mi][ni][3]);
        }
    }
}

__global__ void ktrans_split(const float* __restrict__ in,
                             __nv_bfloat16* __restrict__ oh,
                             __nv_bfloat16* __restrict__ ol, int R, int C) {
    __shared__ float t[32][33];
    const int bx = blockIdx.x * 32;
    const int by = blockIdx.y * 32;
    for (int i = threadIdx.y; i < 32; i += 8)
        t[i][threadIdx.x] = in[(size_t)(by + i) * C + bx + threadIdx.x];
    __syncthreads();
    for (int i = threadIdx.y; i < 32; i += 8) {
        float v = t[threadIdx.x][i];
        size_t o = (size_t)(bx + i) * R + by + threadIdx.x;
        __nv_bfloat16 hb = __float2bfloat16(v);
        oh[o] = hb;
        ol[o] = __float2bfloat16(v - __bfloat162float(hb));
    }
}

__global__ void ksplit(const float* __restrict__ in, __nv_bfloat16* __restrict__ oh,
                       __nv_bfloat16* __restrict__ ol, int n) {
    int i = blockIdx.x * 256 + threadIdx.x;
    if (i < n) {
        float v = in[i];
        __nv_bfloat16 hb = __float2bfloat16(v);
        oh[i] = hb;
        ol[i] = __float2bfloat16(v - __bfloat162float(hb));
    }
}

extern "C" void kernel_launch(void* const* d_in, const int* in_sizes, int n_in,
                              void* d_out, int out_size) {
    const float* y_init = (const float*)d_in[0];
    const float* tspan = (const float*)d_in[1];
    const float* W1 = (const float*)d_in[2];
    const float* b1 = (const float*)d_in[3];
    const float* W2 = (const float*)d_in[4];
    const float* b2 = (const float*)d_in[5];
    float* out = (float*)d_out;

    __nv_bfloat16 *W1h, *W1l, *W2h, *W2l, *Hh, *Hl, *Yh, *Yl;
    float* Yacc;
    cudaGetSymbolAddress((void**)&W1h, g_W1h);
    cudaGetSymbolAddress((void**)&W1l, g_W1l);
    cudaGetSymbolAddress((void**)&W2h, g_W2h);
    cudaGetSymbolAddress((void**)&W2l, g_W2l);
    cudaGetSymbolAddress((void**)&Hh, g_Hh);
    cudaGetSymbolAddress((void**)&Hl, g_Hl);
    cudaGetSymbolAddress((void**)&Yh, g_Yh);
    cudaGetSymbolAddress((void**)&Yl, g_Yl);
    cudaGetSymbolAddress((void**)&Yacc, g_Yacc);

    // dynamic smem: 2 stages x (2 A planes + 2 B planes), BN=128
    const int SM1 = 2 * (2 * 128 * 128 + 2 * 128 * 128);  // 131072 (BM=128)
    const int SM2 = 2 * (2 * 64 * 128 + 2 * 128 * 128);   // 98304  (BM=64)
    cudaFuncSetAttribute(hmma_gemm<128, 0>, cudaFuncAttributeMaxDynamicSharedMemorySize, SM1);
    cudaFuncSetAttribute(hmma_gemm<64, 1>, cudaFuncAttributeMaxDynamicSharedMemorySize, SM2);
    cudaFuncSetAttribute(hmma_gemm<64, 2>, cudaFuncAttributeMaxDynamicSharedMemorySize, SM2);
    cudaFuncSetAttribute(hmma_gemm<64, 3>, cudaFuncAttributeMaxDynamicSharedMemorySize, SM2);
    cudaFuncSetAttribute(hmma_gemm<64, 4>, cudaFuncAttributeMaxDynamicSharedMemorySize, SM2);

    // out = [ t_span (16) | traj (16 x 1024 x 1024) ], traj[0] = y_init
    cudaMemcpyAsync(out, tspan, TSTEPS * sizeof(float), cudaMemcpyDeviceToDevice, 0);
    float* traj = out + TSTEPS;
    cudaMemcpyAsync(traj, y_init, (size_t)BD * sizeof(float), cudaMemcpyDeviceToDevice, 0);

    ktrans_split<<<dim3(HID / 32, DIM / 32), dim3(32, 8)>>>(W1, W1h, W1l, DIM, HID);
    ktrans_split<<<dim3(DIM / 32, HID / 32), dim3(32, 8)>>>(W2, W2h, W2l, HID, DIM);
    ksplit<<<BD / 256, 256>>>(y_init, Yh, Yl, BD);

    const dim3 g1(HID / 128, BATCH / 128);  // (32, 8) = 256 CTAs, BM=128
    const dim3 g2(DIM / 128, BATCH / 64);   // (8, 16) = 128 CTAs, BM=64

    for (int s = 0; s < TSTEPS - 1; ++s) {
        const float* y = traj + (size_t)s * BD;
        float* ynext = traj + (size_t)(s + 1) * BD;

        hmma_gemm<128, 0><<<g1, 256, SM1>>>(Yh, Yl, W1h, W1l, b1, DIM, HID,
                                            Hh, Hl, nullptr, nullptr, nullptr, tspan, s);
        hmma_gemm<64, 1><<<g2, 256, SM2>>>(Hh, Hl, W2h, W2l, b2, HID, DIM,
                                           Yh, Yl, y, Yacc, nullptr, tspan, s);
        hmma_gemm<128, 0><<<g1, 256, SM1>>>(Yh, Yl, W1h, W1l, b1, DIM, HID,
                                            Hh, Hl, nullptr, nullptr, nullptr, tspan, s);
        hmma_gemm<64, 2><<<g2, 256, SM2>>>(Hh, Hl, W2h, W2l, b2, HID, DIM,
                                           Yh, Yl, y, Yacc, nullptr, tspan, s);
        hmma_gemm<128, 0><<<g1, 256, SM1>>>(Yh, Yl, W1h, W1l, b1, DIM, HID,
                                            Hh, Hl, nullptr, nullptr, nullptr, tspan, s);
        hmma_gemm<64, 3><<<g2, 256, SM2>>>(Hh, Hl, W2h, W2l, b2, HID, DIM,
                                           Yh, Yl, y, Yacc, nullptr, tspan, s);
        hmma_gemm<128, 0><<<g1, 256, SM1>>>(Yh, Yl, W1h, W1l, b1, DIM, HID,
                                            Hh, Hl, nullptr, nullptr, nullptr, tspan, s);
        hmma_gemm<64, 4><<<g2, 256, SM2>>>(Hh, Hl, W2h, W2l, b2, HID, DIM,
                                           Yh, Yl, nullptr, Yacc, ynext, tspan, s);
    }
}

// round 8
// speedup vs baseline: 1.5286x; 1.5286x over previous
#include <cuda_runtime.h>
#include <cuda_fp16.h>
#include <cstdint>
#include <cstddef>
#include <cstring>

#define BATCH 1024
#define DIM   1024
#define HID   4096
#define TSTEPS 16
#define BD (BATCH*DIM)

__device__ __half g_W1h[(size_t)HID * DIM];
__device__ __half g_W1l[(size_t)HID * DIM];
__device__ __half g_W2h[(size_t)DIM * HID];
__device__ __half g_W2l[(size_t)DIM * HID];
__device__ __half g_Hh[(size_t)BATCH * HID];
__device__ __half g_Yh[BD];
__device__ float  g_Yacc[BD];
__device__ float  g_P[(size_t)4 * BD];   // split-K partials

__device__ __forceinline__ uint32_t h2_bits(__half2 v) {
    uint32_t u;
    memcpy(&u, &v, 4);
    return u;
}

__device__ __forceinline__ uint32_t smem_u32(const void* p) {
    uint32_t a;
    asm("{ .reg .u64 t; cvta.to.shared.u64 t, %1; cvt.u32.u64 %0, t; }" : "=r"(a) : "l"(p));
    return a;
}
__device__ __forceinline__ void cpa16(uint32_t s, const void* g) {
    asm volatile("cp.async.cg.shared.global [%0], [%1], 16;"
                 :: "r"(s), "l"(__cvta_generic_to_global(g)));
}
#define CP_COMMIT() asm volatile("cp.async.commit_group;" ::: "memory")
#define CP_WAIT0()  asm volatile("cp.async.wait_group 0;" ::: "memory")

__device__ __forceinline__ void ldsm4(uint32_t* r, uint32_t addr) {
    asm volatile("ldmatrix.sync.aligned.m8n8.x4.shared.b16 {%0,%1,%2,%3}, [%4];"
                 : "=r"(r[0]), "=r"(r[1]), "=r"(r[2]), "=r"(r[3]) : "r"(addr));
}
__device__ __forceinline__ void mma_f16(float* d, const uint32_t* a, const uint32_t* b) {
    asm volatile(
        "mma.sync.aligned.m16n8k16.row.col.f32.f16.f16.f32 "
        "{%0,%1,%2,%3}, {%4,%5,%6,%7}, {%8,%9}, {%0,%1,%2,%3};"
        : "+f"(d[0]), "+f"(d[1]), "+f"(d[2]), "+f"(d[3])
        : "r"(a[0]), "r"(a[1]), "r"(a[2]), "r"(a[3]), "r"(b[0]), "r"(b[1]));
}

// -------- GEMM1: H = tanh(Y @ W1^T + b1).  A = Yh fp16 [1024,1024] (1 plane),
// B = W1 planes [4096,1024].  BM=128, BN=256, BK=64, 2-term (Ah*Bh + Ah*Bl).
__global__ void __launch_bounds__(256, 1)
hgemm1(const __half* __restrict__ A, const __half* __restrict__ Bh,
       const __half* __restrict__ Bl, const float* __restrict__ bias,
       __half* __restrict__ H) {
    constexpr int K = 1024;
    constexpr int APLANE = 128 * 128;       // 16 KB
    constexpr int BPLANE = 256 * 128;       // 32 KB
    constexpr int STAGE = APLANE + 2 * BPLANE;
    extern __shared__ char smem[];
    const uint32_t sb0 = smem_u32(smem);

    const int tid = threadIdx.x;
    const int wid = tid >> 5, lane = tid & 31;
    const int wm = wid & 1, wn = wid >> 1;     // 2(M) x 4(N)
    const int gid = lane >> 2, tig = lane & 3;
    const int rowBase = blockIdx.y * 128;
    const int colBase = blockIdx.x * 256;

    auto load_stage = [&](int kc, int st) {
        const uint32_t sb = sb0 + st * STAGE;
        const size_t keB = (size_t)kc * 128;
#pragma unroll
        for (int c = tid; c < 128 * 8; c += 256) {
            const int row = c >> 3, kb = (c & 7) << 4;
            const uint32_t so = row * 128 + (kb ^ ((row & 7) << 4));
            cpa16(sb + so, (const char*)A + (size_t)(rowBase + row) * (K * 2) + keB + kb);
        }
#pragma unroll
        for (int c = tid; c < 256 * 8; c += 256) {
            const int row = c >> 3, kb = (c & 7) << 4;
            const uint32_t so = row * 128 + (kb ^ ((row & 7) << 4));
            const size_t g = (size_t)(colBase + row) * (K * 2) + keB + kb;
            cpa16(sb + APLANE + so, (const char*)Bh + g);
            cpa16(sb + APLANE + BPLANE + so, (const char*)Bl + g);
        }
    };

    float acc[4][8][4];
#pragma unroll
    for (int i = 0; i < 4; ++i)
#pragma unroll
        for (int j = 0; j < 8; ++j)
#pragma unroll
            for (int e = 0; e < 4; ++e) acc[i][j][e] = 0.f;

    load_stage(0, 0);
    CP_COMMIT();

    for (int kc = 0; kc < 16; ++kc) {
        CP_WAIT0();
        __syncthreads();
        if (kc + 1 < 16) { load_stage(kc + 1, (kc + 1) & 1); CP_COMMIT(); }
        const uint32_t sb = sb0 + (kc & 1) * STAGE;
#pragma unroll
        for (int t = 0; t < 4; ++t) {
            uint32_t af[4][4];
#pragma unroll
            for (int mi = 0; mi < 4; ++mi) {
                const int arow = wm * 64 + mi * 16 + (lane & 15);
                const int kb = t * 32 + ((lane >> 4) << 4);
                ldsm4(af[mi], sb + arow * 128 + (kb ^ ((arow & 7) << 4)));
            }
            uint32_t bf[16];
#pragma unroll
            for (int pl = 0; pl < 2; ++pl) {
                const uint32_t bbase = sb + APLANE + pl * BPLANE;
#pragma unroll
                for (int bi = 0; bi < 4; ++bi) {
                    const int brow = wn * 64 + bi * 16 + ((lane >> 4) << 3) + (lane & 7);
                    const int kb = t * 32 + (((lane >> 3) & 1) << 4);
                    ldsm4(&bf[bi * 4], bbase + brow * 128 + (kb ^ ((brow & 7) << 4)));
                }
#pragma unroll
                for (int mi = 0; mi < 4; ++mi)
#pragma unroll
                    for (int ni = 0; ni < 8; ++ni)
                        mma_f16(acc[mi][ni], af[mi], &bf[ni * 2]);
            }
        }
    }

#pragma unroll
    for (int mi = 0; mi < 4; ++mi) {
#pragma unroll
        for (int ni = 0; ni < 8; ++ni) {
            const int col = colBase + wn * 64 + ni * 8 + tig * 2;
            const float2 bb = *reinterpret_cast<const float2*>(bias + col);
#pragma unroll
            for (int half = 0; half < 2; ++half) {
                const int row = rowBase + wm * 64 + mi * 16 + gid + half * 8;
                const float v0 = tanhf(acc[mi][ni][half * 2 + 0] + bb.x);
                const float v1 = tanhf(acc[mi][ni][half * 2 + 1] + bb.y);
                *reinterpret_cast<__half2*>(H + (size_t)row * HID + col) =
                    __floats2half2_rn(v0, v1);
            }
        }
    }
}

// -------- GEMM2 (split-K): P[kz] = H @ W2^T  (partial over K slice of 1024).
// A = Hh [1024,4096], B = W2 planes [1024,4096]. BM=BN=128.
__global__ void __launch_bounds__(256, 2)
hgemm2(const __half* __restrict__ A, const __half* __restrict__ Bh,
       const __half* __restrict__ Bl, float* __restrict__ P) {
    constexpr int K = 4096;
    constexpr int APLANE = 128 * 128;
    constexpr int BPLANE = 128 * 128;
    constexpr int STAGE = APLANE + 2 * BPLANE;  // 48 KB
    extern __shared__ char smem[];
    const uint32_t sb0 = smem_u32(smem);

    const int tid = threadIdx.x;
    const int wid = tid >> 5, lane = tid & 31;
    const int wm = wid & 1, wn = wid >> 1;
    const int gid = lane >> 2, tig = lane & 3;
    const int rowBase = blockIdx.y * 128;
    const int colBase = blockIdx.x * 128;
    const size_t kzB = (size_t)blockIdx.z * 2048;  // 1024 fp16 = 2048 bytes

    auto load_stage = [&](int kc, int st) {
        const uint32_t sb = sb0 + st * STAGE;
        const size_t keB = kzB + (size_t)kc * 128;
#pragma unroll
        for (int c = tid; c < 128 * 8; c += 256) {
            const int row = c >> 3, kb = (c & 7) << 4;
            const uint32_t so = row * 128 + (kb ^ ((row & 7) << 4));
            cpa16(sb + so, (const char*)A + (size_t)(rowBase + row) * (K * 2) + keB + kb);
            const size_t g = (size_t)(colBase + row) * (K * 2) + keB + kb;
            cpa16(sb + APLANE + so, (const char*)Bh + g);
            cpa16(sb + APLANE + BPLANE + so, (const char*)Bl + g);
        }
    };

    float acc[4][4][4];
#pragma unroll
    for (int i = 0; i < 4; ++i)
#pragma unroll
        for (int j = 0; j < 4; ++j)
#pragma unroll
            for (int e = 0; e < 4; ++e) acc[i][j][e] = 0.f;

    load_stage(0, 0);
    CP_COMMIT();

    for (int kc = 0; kc < 16; ++kc) {
        CP_WAIT0();
        __syncthreads();
        if (kc + 1 < 16) { load_stage(kc + 1, (kc + 1) & 1); CP_COMMIT(); }
        const uint32_t sb = sb0 + (kc & 1) * STAGE;
#pragma unroll
        for (int t = 0; t < 4; ++t) {
            uint32_t af[4][4];
#pragma unroll
            for (int mi = 0; mi < 4; ++mi) {
                const int arow = wm * 64 + mi * 16 + (lane & 15);
                const int kb = t * 32 + ((lane >> 4) << 4);
                ldsm4(af[mi], sb + arow * 128 + (kb ^ ((arow & 7) << 4)));
            }
#pragma unroll
            for (int pl = 0; pl < 2; ++pl) {
                const uint32_t bbase = sb + APLANE + pl * BPLANE;
                uint32_t bf[8];
#pragma unroll
                for (int bi = 0; bi < 2; ++bi) {
                    const int brow = wn * 32 + bi * 16 + ((lane >> 4) << 3) + (lane & 7);
                    const int kb = t * 32 + (((lane >> 3) & 1) << 4);
                    ldsm4(&bf[bi * 4], bbase + brow * 128 + (kb ^ ((brow & 7) << 4)));
                }
#pragma unroll
                for (int mi = 0; mi < 4; ++mi)
#pragma unroll
                    for (int ni = 0; ni < 4; ++ni)
                        mma_f16(acc[mi][ni], af[mi], &bf[ni * 2]);
            }
        }
    }

    float* Pz = P + (size_t)blockIdx.z * BD;
#pragma unroll
    for (int mi = 0; mi < 4; ++mi) {
#pragma unroll
        for (int ni = 0; ni < 4; ++ni) {
            const int col = colBase + wn * 32 + ni * 8 + tig * 2;
#pragma unroll
            for (int half = 0; half < 2; ++half) {
                const int row = rowBase + wm * 64 + mi * 16 + gid + half * 8;
                float2 v;
                v.x = acc[mi][ni][half * 2 + 0];
                v.y = acc[mi][ni][half * 2 + 1];
                *reinterpret_cast<float2*>(Pz + (size_t)row * DIM + col) = v;
            }
        }
    }
}

// -------- reduce + RK4 stage update (fp32 master state chain) --------
template <int EPI>
__global__ void kreduce(const float* __restrict__ P, const float* __restrict__ b2,
                        const float* __restrict__ ybase, float* __restrict__ Yacc,
                        float* __restrict__ yout, __half* __restrict__ Yh,
                        const float* __restrict__ tspan, int step) {
    const int idx = blockIdx.x * 256 + threadIdx.x;
    const size_t i4 = (size_t)idx * 4;
    const float h = tspan[step + 1] - tspan[step];
    float4 k = *reinterpret_cast<const float4*>(P + i4);
    const float4 k1 = *reinterpret_cast<const float4*>(P + BD + i4);
    const float4 k2 = *reinterpret_cast<const float4*>(P + 2 * (size_t)BD + i4);
    const float4 k3 = *reinterpret_cast<const float4*>(P + 3 * (size_t)BD + i4);
    const float4 bb = *reinterpret_cast<const float4*>(b2 + (i4 & 1023));
    k.x += k1.x + k2.x + k3.x + bb.x;
    k.y += k1.y + k2.y + k3.y + bb.y;
    k.z += k1.z + k2.z + k3.z + bb.z;
    k.w += k1.w + k2.w + k3.w + bb.w;

    float4 o;
    if (EPI == 4) {
        const float4 aa = *reinterpret_cast<const float4*>(Yacc + i4);
        o.x = fmaf(h * (1.f / 6.f), k.x, aa.x);
        o.y = fmaf(h * (1.f / 6.f), k.y, aa.y);
        o.z = fmaf(h * (1.f / 6.f), k.z, aa.z);
        o.w = fmaf(h * (1.f / 6.f), k.w, aa.w);
        *reinterpret_cast<float4*>(yout + i4) = o;
    } else {
        const float4 yy = *reinterpret_cast<const float4*>(ybase + i4);
        const float cy = (EPI == 3) ? 1.0f : 0.5f;
        o.x = fmaf(cy * h, k.x, yy.x);
        o.y = fmaf(cy * h, k.y, yy.y);
        o.z = fmaf(cy * h, k.z, yy.z);
        o.w = fmaf(cy * h, k.w, yy.w);
        float4 aa;
        if (EPI == 1) {
            aa.x = fmaf(h * (1.f / 6.f), k.x, yy.x);
            aa.y = fmaf(h * (1.f / 6.f), k.y, yy.y);
            aa.z = fmaf(h * (1.f / 6.f), k.z, yy.z);
            aa.w = fmaf(h * (1.f / 6.f), k.w, yy.w);
        } else {
            aa = *reinterpret_cast<const float4*>(Yacc + i4);
            aa.x = fmaf(h * (1.f / 3.f), k.x, aa.x);
            aa.y = fmaf(h * (1.f / 3.f), k.y, aa.y);
            aa.z = fmaf(h * (1.f / 3.f), k.z, aa.z);
            aa.w = fmaf(h * (1.f / 3.f), k.w, aa.w);
        }
        *reinterpret_cast<float4*>(Yacc + i4) = aa;
    }
    uint2 hp;
    hp.x = h2_bits(__floats2half2_rn(o.x, o.y));
    hp.y = h2_bits(__floats2half2_rn(o.z, o.w));
    *reinterpret_cast<uint2*>(Yh + i4) = hp;
}

// fp32 [R,C] -> fp16 hi/lo planes [C,R]
__global__ void ktrans_split_h(const float* __restrict__ in, __half* __restrict__ oh,
                               __half* __restrict__ ol, int R, int C) {
    __shared__ float t[32][33];
    const int bx = blockIdx.x * 32;
    const int by = blockIdx.y * 32;
    for (int i = threadIdx.y; i < 32; i += 8)
        t[i][threadIdx.x] = in[(size_t)(by + i) * C + bx + threadIdx.x];
    __syncthreads();
    for (int i = threadIdx.y; i < 32; i += 8) {
        float v = t[threadIdx.x][i];
        size_t o = (size_t)(bx + i) * R + by + threadIdx.x;
        __half hv = __float2half(v);
        oh[o] = hv;
        ol[o] = __float2half(v - __half2float(hv));
    }
}

__global__ void ky(const float* __restrict__ in, __half* __restrict__ oh, int n) {
    int i = blockIdx.x * 256 + threadIdx.x;
    if (i < n) oh[i] = __float2half(in[i]);
}

extern "C" void kernel_launch(void* const* d_in, const int* in_sizes, int n_in,
                              void* d_out, int out_size) {
    const float* y_init = (const float*)d_in[0];
    const float* tspan = (const float*)d_in[1];
    const float* W1 = (const float*)d_in[2];
    const float* b1 = (const float*)d_in[3];
    const float* W2 = (const float*)d_in[4];
    const float* b2 = (const float*)d_in[5];
    float* out = (float*)d_out;

    __half *W1h, *W1l, *W2h, *W2l, *Hh, *Yh;
    float *Yacc, *P;
    cudaGetSymbolAddress((void**)&W1h, g_W1h);
    cudaGetSymbolAddress((void**)&W1l, g_W1l);
    cudaGetSymbolAddress((void**)&W2h, g_W2h);
    cudaGetSymbolAddress((void**)&W2l, g_W2l);
    cudaGetSymbolAddress((void**)&Hh, g_Hh);
    cudaGetSymbolAddress((void**)&Yh, g_Yh);
    cudaGetSymbolAddress((void**)&Yacc, g_Yacc);
    cudaGetSymbolAddress((void**)&P, g_P);

    const int SM1 = 2 * (128 * 128 + 2 * 256 * 128);  // 163840
    const int SM2 = 2 * (128 * 128 + 2 * 128 * 128);  // 98304
    cudaFuncSetAttribute(hgemm1, cudaFuncAttributeMaxDynamicSharedMemorySize, SM1);
    cudaFuncSetAttribute(hgemm2, cudaFuncAttributeMaxDynamicSharedMemorySize, SM2);

    cudaMemcpyAsync(out, tspan, TSTEPS * sizeof(float), cudaMemcpyDeviceToDevice, 0);
    float* traj = out + TSTEPS;
    cudaMemcpyAsync(traj, y_init, (size_t)BD * sizeof(float), cudaMemcpyDeviceToDevice, 0);

    ktrans_split_h<<<dim3(HID / 32, DIM / 32), dim3(32, 8)>>>(W1, W1h, W1l, DIM, HID);
    ktrans_split_h<<<dim3(DIM / 32, HID / 32), dim3(32, 8)>>>(W2, W2h, W2l, HID, DIM);
    ky<<<BD / 256, 256>>>(y_init, Yh, BD);

    const dim3 g1(HID / 256, BATCH / 128);      // (16, 8) = 128 CTAs
    const dim3 g2(DIM / 128, BATCH / 128, 4);   // (8, 8, 4) = 256 CTAs (split-K)

    for (int s = 0; s < TSTEPS - 1; ++s) {
        const float* y = traj + (size_t)s * BD;
        float* ynext = traj + (size_t)(s + 1) * BD;

        hgemm1<<<g1, 256, SM1>>>(Yh, W1h, W1l, b1, Hh);
        hgemm2<<<g2, 256, SM2>>>(Hh, W2h, W2l, P);
        kreduce<1><<<BD / 1024, 256>>>(P, b2, y, Yacc, nullptr, Yh, tspan, s);

        hgemm1<<<g1, 256, SM1>>>(Yh, W1h, W1l, b1, Hh);
        hgemm2<<<g2, 256, SM2>>>(Hh, W2h, W2l, P);
        kreduce<2><<<BD / 1024, 256>>>(P, b2, y, Yacc, nullptr, Yh, tspan, s);

        hgemm1<<<g1, 256, SM1>>>(Yh, W1h, W1l, b1, Hh);
        hgemm2<<<g2, 256, SM2>>>(Hh, W2h, W2l, P);
        kreduce<3><<<BD / 1024, 256>>>(P, b2, y, Yacc, nullptr, Yh, tspan, s);

        hgemm1<<<g1, 256, SM1>>>(Yh, W1h, W1l, b1, Hh);
        hgemm2<<<g2, 256, SM2>>>(Hh, W2h, W2l, P);
        kreduce<4><<<BD / 1024, 256>>>(P, b2, y, Yacc, ynext, Yh, tspan, s);
    }
}

// round 9
// speedup vs baseline: 2.6369x; 1.7251x over previous
#include <cuda_runtime.h>
#include <cuda_fp16.h>
#include <cstdint>
#include <cstddef>
#include <cstring>

#define BATCH 1024
#define DIM   1024
#define HID   4096
#define TSTEPS 16
#define BD (BATCH*DIM)

__device__ __half g_W1[(size_t)HID * DIM];   // W1^T fp16 [4096,1024]
__device__ __half g_W2[(size_t)DIM * HID];   // W2^T fp16 [1024,4096]
__device__ __half g_H[(size_t)BATCH * HID];  // hidden fp16
__device__ __half g_Yh[BD];                  // state fp16 (rounded)
__device__ float  g_Yacc[BD];                // RK4 accumulator (fp32)
__device__ float  g_P[(size_t)4 * BD];       // split-K partials

__device__ __forceinline__ uint32_t h2_bits(__half2 v) {
    uint32_t u;
    memcpy(&u, &v, 4);
    return u;
}
__device__ __forceinline__ uint32_t smem_u32(const void* p) {
    uint32_t a;
    asm("{ .reg .u64 t; cvta.to.shared.u64 t, %1; cvt.u32.u64 %0, t; }" : "=r"(a) : "l"(p));
    return a;
}
__device__ __forceinline__ void cpa16(uint32_t s, const void* g) {
    asm volatile("cp.async.cg.shared.global [%0], [%1], 16;"
                 :: "r"(s), "l"(__cvta_generic_to_global(g)));
}
#define CP_COMMIT() asm volatile("cp.async.commit_group;" ::: "memory")
#define CP_WAIT0()  asm volatile("cp.async.wait_group 0;" ::: "memory")

__device__ __forceinline__ void ldsm4(uint32_t* r, uint32_t addr) {
    asm volatile("ldmatrix.sync.aligned.m8n8.x4.shared.b16 {%0,%1,%2,%3}, [%4];"
                 : "=r"(r[0]), "=r"(r[1]), "=r"(r[2]), "=r"(r[3]) : "r"(addr));
}
__device__ __forceinline__ void mma_f16(float* d, const uint32_t* a, const uint32_t* b) {
    asm volatile(
        "mma.sync.aligned.m16n8k16.row.col.f32.f16.f16.f32 "
        "{%0,%1,%2,%3}, {%4,%5,%6,%7}, {%8,%9}, {%0,%1,%2,%3};"
        : "+f"(d[0]), "+f"(d[1]), "+f"(d[2]), "+f"(d[3])
        : "r"(a[0]), "r"(a[1]), "r"(a[2]), "r"(a[3]), "r"(b[0]), "r"(b[1]));
}

// -------- GEMM1: H = tanh(Y @ W1^T + b1). BM=128, BN=128, BK=64, 1 plane each.
// 256 thr, warps 2(M)x4(N), warp tile 64x32. 2 CTAs/SM.
__global__ void __launch_bounds__(256, 2)
hgemm1(const __half* __restrict__ A, const __half* __restrict__ B,
       const float* __restrict__ bias, __half* __restrict__ H) {
    constexpr int K = 1024;
    constexpr int APLANE = 128 * 128;   // 16 KB
    constexpr int BPLANE = 128 * 128;   // 16 KB
    constexpr int STAGE = APLANE + BPLANE;
    extern __shared__ char smem[];
    const uint32_t sb0 = smem_u32(smem);

    const int tid = threadIdx.x;
    const int wid = tid >> 5, lane = tid & 31;
    const int wm = wid & 1, wn = wid >> 1;
    const int gid = lane >> 2, tig = lane & 3;
    const int rowBase = blockIdx.y * 128;
    const int colBase = blockIdx.x * 128;

    auto load_stage = [&](int kc, int st) {
        const uint32_t sb = sb0 + st * STAGE;
        const size_t keB = (size_t)kc * 128;
#pragma unroll
        for (int c = tid; c < 128 * 8; c += 256) {
            const int row = c >> 3, kb = (c & 7) << 4;
            const uint32_t so = row * 128 + (kb ^ ((row & 7) << 4));
            cpa16(sb + so, (const char*)A + (size_t)(rowBase + row) * (K * 2) + keB + kb);
            cpa16(sb + APLANE + so,
                  (const char*)B + (size_t)(colBase + row) * (K * 2) + keB + kb);
        }
    };

    float acc[4][4][4];
#pragma unroll
    for (int i = 0; i < 4; ++i)
#pragma unroll
        for (int j = 0; j < 4; ++j)
#pragma unroll
            for (int e = 0; e < 4; ++e) acc[i][j][e] = 0.f;

    load_stage(0, 0);
    CP_COMMIT();

    for (int kc = 0; kc < 16; ++kc) {
        CP_WAIT0();
        __syncthreads();
        if (kc + 1 < 16) { load_stage(kc + 1, (kc + 1) & 1); CP_COMMIT(); }
        const uint32_t sb = sb0 + (kc & 1) * STAGE;
#pragma unroll
        for (int t = 0; t < 4; ++t) {
            uint32_t af[4][4];
#pragma unroll
            for (int mi = 0; mi < 4; ++mi) {
                const int arow = wm * 64 + mi * 16 + (lane & 15);
                const int kb = t * 32 + ((lane >> 4) << 4);
                ldsm4(af[mi], sb + arow * 128 + (kb ^ ((arow & 7) << 4)));
            }
            uint32_t bf[8];
#pragma unroll
            for (int bi = 0; bi < 2; ++bi) {
                const int brow = wn * 32 + bi * 16 + ((lane >> 4) << 3) + (lane & 7);
                const int kb = t * 32 + (((lane >> 3) & 1) << 4);
                ldsm4(&bf[bi * 4], sb + APLANE + brow * 128 + (kb ^ ((brow & 7) << 4)));
            }
#pragma unroll
            for (int mi = 0; mi < 4; ++mi)
#pragma unroll
                for (int ni = 0; ni < 4; ++ni)
                    mma_f16(acc[mi][ni], af[mi], &bf[ni * 2]);
        }
    }

#pragma unroll
    for (int mi = 0; mi < 4; ++mi) {
#pragma unroll
        for (int ni = 0; ni < 4; ++ni) {
            const int col = colBase + wn * 32 + ni * 8 + tig * 2;
            const float2 bb = *reinterpret_cast<const float2*>(bias + col);
#pragma unroll
            for (int half = 0; half < 2; ++half) {
                const int row = rowBase + wm * 64 + mi * 16 + gid + half * 8;
                const float v0 = tanhf(acc[mi][ni][half * 2 + 0] + bb.x);
                const float v1 = tanhf(acc[mi][ni][half * 2 + 1] + bb.y);
                *reinterpret_cast<__half2*>(H + (size_t)row * HID + col) =
                    __floats2half2_rn(v0, v1);
            }
        }
    }
}

// -------- GEMM2 (split-K x4): P[kz] = H @ W2^T (K slice of 1024). BM=BN=128.
__global__ void __launch_bounds__(256, 2)
hgemm2(const __half* __restrict__ A, const __half* __restrict__ B,
       float* __restrict__ P) {
    constexpr int K = 4096;
    constexpr int APLANE = 128 * 128;
    constexpr int BPLANE = 128 * 128;
    constexpr int STAGE = APLANE + BPLANE;  // 32 KB
    extern __shared__ char smem[];
    const uint32_t sb0 = smem_u32(smem);

    const int tid = threadIdx.x;
    const int wid = tid >> 5, lane = tid & 31;
    const int wm = wid & 1, wn = wid >> 1;
    const int gid = lane >> 2, tig = lane & 3;
    const int rowBase = blockIdx.y * 128;
    const int colBase = blockIdx.x * 128;
    const size_t kzB = (size_t)blockIdx.z * 2048;

    auto load_stage = [&](int kc, int st) {
        const uint32_t sb = sb0 + st * STAGE;
        const size_t keB = kzB + (size_t)kc * 128;
#pragma unroll
        for (int c = tid; c < 128 * 8; c += 256) {
            const int row = c >> 3, kb = (c & 7) << 4;
            const uint32_t so = row * 128 + (kb ^ ((row & 7) << 4));
            cpa16(sb + so, (const char*)A + (size_t)(rowBase + row) * (K * 2) + keB + kb);
            cpa16(sb + APLANE + so,
                  (const char*)B + (size_t)(colBase + row) * (K * 2) + keB + kb);
        }
    };

    float acc[4][4][4];
#pragma unroll
    for (int i = 0; i < 4; ++i)
#pragma unroll
        for (int j = 0; j < 4; ++j)
#pragma unroll
            for (int e = 0; e < 4; ++e) acc[i][j][e] = 0.f;

    load_stage(0, 0);
    CP_COMMIT();

    for (int kc = 0; kc < 16; ++kc) {
        CP_WAIT0();
        __syncthreads();
        if (kc + 1 < 16) { load_stage(kc + 1, (kc + 1) & 1); CP_COMMIT(); }
        const uint32_t sb = sb0 + (kc & 1) * STAGE;
#pragma unroll
        for (int t = 0; t < 4; ++t) {
            uint32_t af[4][4];
#pragma unroll
            for (int mi = 0; mi < 4; ++mi) {
                const int arow = wm * 64 + mi * 16 + (lane & 15);
                const int kb = t * 32 + ((lane >> 4) << 4);
                ldsm4(af[mi], sb + arow * 128 + (kb ^ ((arow & 7) << 4)));
            }
            uint32_t bf[8];
#pragma unroll
            for (int bi = 0; bi < 2; ++bi) {
                const int brow = wn * 32 + bi * 16 + ((lane >> 4) << 3) + (lane & 7);
                const int kb = t * 32 + (((lane >> 3) & 1) << 4);
                ldsm4(&bf[bi * 4], sb + APLANE + brow * 128 + (kb ^ ((brow & 7) << 4)));
            }
#pragma unroll
            for (int mi = 0; mi < 4; ++mi)
#pragma unroll
                for (int ni = 0; ni < 4; ++ni)
                    mma_f16(acc[mi][ni], af[mi], &bf[ni * 2]);
        }
    }

    float* Pz = P + (size_t)blockIdx.z * BD;
#pragma unroll
    for (int mi = 0; mi < 4; ++mi) {
#pragma unroll
        for (int ni = 0; ni < 4; ++ni) {
            const int col = colBase + wn * 32 + ni * 8 + tig * 2;
#pragma unroll
            for (int half = 0; half < 2; ++half) {
                const int row = rowBase + wm * 64 + mi * 16 + gid + half * 8;
                float2 v;
                v.x = acc[mi][ni][half * 2 + 0];
                v.y = acc[mi][ni][half * 2 + 1];
                *reinterpret_cast<float2*>(Pz + (size_t)row * DIM + col) = v;
            }
        }
    }
}

// -------- reduce + RK4 stage update (fp32 master state chain) --------
template <int EPI>
__global__ void kreduce(const float* __restrict__ P, const float* __restrict__ b2,
                        const float* __restrict__ ybase, float* __restrict__ Yacc,
                        float* __restrict__ yout, __half* __restrict__ Yh,
                        const float* __restrict__ tspan, int step) {
    const int idx = blockIdx.x * 256 + threadIdx.x;
    const size_t i4 = (size_t)idx * 4;
    const float h = tspan[step + 1] - tspan[step];
    float4 k = *reinterpret_cast<const float4*>(P + i4);
    const float4 k1 = *reinterpret_cast<const float4*>(P + BD + i4);
    const float4 k2 = *reinterpret_cast<const float4*>(P + 2 * (size_t)BD + i4);
    const float4 k3 = *reinterpret_cast<const float4*>(P + 3 * (size_t)BD + i4);
    const float4 bb = *reinterpret_cast<const float4*>(b2 + (i4 & 1023));
    k.x += k1.x + k2.x + k3.x + bb.x;
    k.y += k1.y + k2.y + k3.y + bb.y;
    k.z += k1.z + k2.z + k3.z + bb.z;
    k.w += k1.w + k2.w + k3.w + bb.w;

    float4 o;
    if (EPI == 4) {
        const float4 aa = *reinterpret_cast<const float4*>(Yacc + i4);
        o.x = fmaf(h * (1.f / 6.f), k.x, aa.x);
        o.y = fmaf(h * (1.f / 6.f), k.y, aa.y);
        o.z = fmaf(h * (1.f / 6.f), k.z, aa.z);
        o.w = fmaf(h * (1.f / 6.f), k.w, aa.w);
        *reinterpret_cast<float4*>(yout + i4) = o;
    } else {
        const float4 yy = *reinterpret_cast<const float4*>(ybase + i4);
        const float cy = (EPI == 3) ? 1.0f : 0.5f;
        o.x = fmaf(cy * h, k.x, yy.x);
        o.y = fmaf(cy * h, k.y, yy.y);
        o.z = fmaf(cy * h, k.z, yy.z);
        o.w = fmaf(cy * h, k.w, yy.w);
        float4 aa;
        if (EPI == 1) {
            aa.x = fmaf(h * (1.f / 6.f), k.x, yy.x);
            aa.y = fmaf(h * (1.f / 6.f), k.y, yy.y);
            aa.z = fmaf(h * (1.f / 6.f), k.z, yy.z);
            aa.w = fmaf(h * (1.f / 6.f), k.w, yy.w);
        } else {
            aa = *reinterpret_cast<const float4*>(Yacc + i4);
            aa.x = fmaf(h * (1.f / 3.f), k.x, aa.x);
            aa.y = fmaf(h * (1.f / 3.f), k.y, aa.y);
            aa.z = fmaf(h * (1.f / 3.f), k.z, aa.z);
            aa.w = fmaf(h * (1.f / 3.f), k.w, aa.w);
        }
        *reinterpret_cast<float4*>(Yacc + i4) = aa;
    }
    uint2 hp;
    hp.x = h2_bits(__floats2half2_rn(o.x, o.y));
    hp.y = h2_bits(__floats2half2_rn(o.z, o.w));
    *reinterpret_cast<uint2*>(Yh + i4) = hp;
}

// fp32 [R,C] -> fp16 plane [C,R] (transpose + round)
__global__ void ktrans_h(const float* __restrict__ in, __half* __restrict__ oh,
                         int R, int C) {
    __shared__ float t[32][33];
    const int bx = blockIdx.x * 32;
    const int by = blockIdx.y * 32;
    for (int i = threadIdx.y; i < 32; i += 8)
        t[i][threadIdx.x] = in[(size_t)(by + i) * C + bx + threadIdx.x];
    __syncthreads();
    for (int i = threadIdx.y; i < 32; i += 8)
        oh[(size_t)(bx + i) * R + by + threadIdx.x] = __float2half(t[threadIdx.x][i]);
}

__global__ void ky(const float* __restrict__ in, __half* __restrict__ oh, int n) {
    int i = blockIdx.x * 256 + threadIdx.x;
    if (i < n) oh[i] = __float2half(in[i]);
}

extern "C" void kernel_launch(void* const* d_in, const int* in_sizes, int n_in,
                              void* d_out, int out_size) {
    const float* y_init = (const float*)d_in[0];
    const float* tspan = (const float*)d_in[1];
    const float* W1 = (const float*)d_in[2];
    const float* b1 = (const float*)d_in[3];
    const float* W2 = (const float*)d_in[4];
    const float* b2 = (const float*)d_in[5];
    float* out = (float*)d_out;

    __half *W1p, *W2p, *H, *Yh;
    float *Yacc, *P;
    cudaGetSymbolAddress((void**)&W1p, g_W1);
    cudaGetSymbolAddress((void**)&W2p, g_W2);
    cudaGetSymbolAddress((void**)&H, g_H);
    cudaGetSymbolAddress((void**)&Yh, g_Yh);
    cudaGetSymbolAddress((void**)&Yacc, g_Yacc);
    cudaGetSymbolAddress((void**)&P, g_P);

    const int SMEM = 2 * (128 * 128 + 128 * 128);  // 65536 both kernels
    cudaFuncSetAttribute(hgemm1, cudaFuncAttributeMaxDynamicSharedMemorySize, SMEM);
    cudaFuncSetAttribute(hgemm2, cudaFuncAttributeMaxDynamicSharedMemorySize, SMEM);

    cudaMemcpyAsync(out, tspan, TSTEPS * sizeof(float), cudaMemcpyDeviceToDevice, 0);
    float* traj = out + TSTEPS;
    cudaMemcpyAsync(traj, y_init, (size_t)BD * sizeof(float), cudaMemcpyDeviceToDevice, 0);

    ktrans_h<<<dim3(HID / 32, DIM / 32), dim3(32, 8)>>>(W1, W1p, DIM, HID);
    ktrans_h<<<dim3(DIM / 32, HID / 32), dim3(32, 8)>>>(W2, W2p, HID, DIM);
    ky<<<BD / 256, 256>>>(y_init, Yh, BD);

    const dim3 g1(HID / 128, BATCH / 128);      // (32, 8) = 256 CTAs
    const dim3 g2(DIM / 128, BATCH / 128, 4);   // (8, 8, 4) = 256 CTAs

    for (int s = 0; s < TSTEPS - 1; ++s) {
        const float* y = traj + (size_t)s * BD;
        float* ynext = traj + (size_t)(s + 1) * BD;

        hgemm1<<<g1, 256, SMEM>>>(Yh, W1p, b1, H);
        hgemm2<<<g2, 256, SMEM>>>(H, W2p, P);
        kreduce<1><<<BD / 1024, 256>>>(P, b2, y, Yacc, nullptr, Yh, tspan, s);

        hgemm1<<<g1, 256, SMEM>>>(Yh, W1p, b1, H);
        hgemm2<<<g2, 256, SMEM>>>(H, W2p, P);
        kreduce<2><<<BD / 1024, 256>>>(P, b2, y, Yacc, nullptr, Yh, tspan, s);

        hgemm1<<<g1, 256, SMEM>>>(Yh, W1p, b1, H);
        hgemm2<<<g2, 256, SMEM>>>(H, W2p, P);
        kreduce<3><<<BD / 1024, 256>>>(P, b2, y, Yacc, nullptr, Yh, tspan, s);

        hgemm1<<<g1, 256, SMEM>>>(Yh, W1p, b1, H);
        hgemm2<<<g2, 256, SMEM>>>(H, W2p, P);
        kreduce<4><<<BD / 1024, 256>>>(P, b2, y, Yacc, ynext, Yh, tspan, s);
    }
}

// round 10
// speedup vs baseline: 2.6510x; 1.0054x over previous
#include <cuda_runtime.h>
#include <cuda_fp16.h>
#include <cstdint>
#include <cstddef>
#include <cstring>

#define BATCH 1024
#define DIM   1024
#define HID   4096
#define TSTEPS 16
#define BD (BATCH*DIM)

__device__ __half g_W1[(size_t)HID * DIM];   // W1^T fp16 [4096,1024]
__device__ __half g_W2[(size_t)DIM * HID];   // W2^T fp16 [1024,4096]
__device__ __half g_H[(size_t)BATCH * HID];  // hidden fp16
__device__ __half g_Yh[BD];                  // state fp16 (rounded)
__device__ float  g_Yacc[BD];                // RK4 accumulator (fp32)
__device__ float  g_P[(size_t)4 * BD];       // split-K partials

__device__ __forceinline__ uint32_t h2_bits(__half2 v) {
    uint32_t u;
    memcpy(&u, &v, 4);
    return u;
}
__device__ __forceinline__ uint32_t smem_u32(const void* p) {
    uint32_t a;
    asm("{ .reg .u64 t; cvta.to.shared.u64 t, %1; cvt.u32.u64 %0, t; }" : "=r"(a) : "l"(p));
    return a;
}
__device__ __forceinline__ void cpa16(uint32_t s, const void* g) {
    asm volatile("cp.async.cg.shared.global [%0], [%1], 16;"
                 :: "r"(s), "l"(__cvta_generic_to_global(g)));
}
#define CP_COMMIT() asm volatile("cp.async.commit_group;" ::: "memory")
#define CP_WAIT1()  asm volatile("cp.async.wait_group 1;" ::: "memory")

__device__ __forceinline__ void ldsm4(uint32_t* r, uint32_t addr) {
    asm volatile("ldmatrix.sync.aligned.m8n8.x4.shared.b16 {%0,%1,%2,%3}, [%4];"
                 : "=r"(r[0]), "=r"(r[1]), "=r"(r[2]), "=r"(r[3]) : "r"(addr));
}
__device__ __forceinline__ void mma_f16(float* d, const uint32_t* a, const uint32_t* b) {
    asm volatile(
        "mma.sync.aligned.m16n8k16.row.col.f32.f16.f16.f32 "
        "{%0,%1,%2,%3}, {%4,%5,%6,%7}, {%8,%9}, {%0,%1,%2,%3};"
        : "+f"(d[0]), "+f"(d[1]), "+f"(d[2]), "+f"(d[3])
        : "r"(a[0]), "r"(a[1]), "r"(a[2]), "r"(a[3]), "r"(b[0]), "r"(b[1]));
}
__device__ __forceinline__ float tanh_fast(float x) {
    asm("tanh.approx.f32 %0, %0;" : "+f"(x));
    return x;
}

// Shared GEMM body: C tile [128 x 128] of A[M,K] @ B[N,K]^T.
// 128 threads = 4 warps (2M x 2N), warp tile 64x64 (MI=4, NT=8).
// 3-stage cp.async pipeline, 2 CTAs/SM.
// EPI=0: H = tanh(acc + bias) fp16 out.  EPI=1: P = acc fp32 out (split-K).
template <int EPI>
__device__ __forceinline__ void gemm_body(
    const __half* A, const __half* B, const float* bias, __half* H,
    float* P, int K, size_t kzB, int NC, char* smem) {
    constexpr int APLANE = 128 * 128;   // 16 KB
    constexpr int STAGE = 2 * APLANE;   // 32 KB
    const uint32_t sb0 = smem_u32(smem);

    const int tid = threadIdx.x;
    const int wid = tid >> 5, lane = tid & 31;
    const int wm = wid & 1, wn = wid >> 1;
    const int gid = lane >> 2, tig = lane & 3;
    const int rowBase = blockIdx.y * 128;
    const int colBase = blockIdx.x * 128;

    auto load_stage = [&](int kc, int st) {
        const uint32_t sb = sb0 + st * STAGE;
        const size_t keB = kzB + (size_t)kc * 128;
#pragma unroll
        for (int c = tid; c < 128 * 8; c += 128) {
            const int row = c >> 3, kb = (c & 7) << 4;
            const uint32_t so = row * 128 + (kb ^ ((row & 7) << 4));
            cpa16(sb + so, (const char*)A + (size_t)(rowBase + row) * (K * 2) + keB + kb);
            cpa16(sb + APLANE + so,
                  (const char*)B + (size_t)(colBase + row) * (K * 2) + keB + kb);
        }
    };

    float acc[4][8][4];
#pragma unroll
    for (int i = 0; i < 4; ++i)
#pragma unroll
        for (int j = 0; j < 8; ++j)
#pragma unroll
            for (int e = 0; e < 4; ++e) acc[i][j][e] = 0.f;

    load_stage(0, 0);
    CP_COMMIT();
    load_stage(1, 1);
    CP_COMMIT();

    for (int kc = 0; kc < NC; ++kc) {
        CP_WAIT1();
        __syncthreads();
        if (kc + 2 < NC) load_stage(kc + 2, (kc + 2) % 3);
        CP_COMMIT();
        const uint32_t sb = sb0 + (kc % 3) * STAGE;
#pragma unroll
        for (int t = 0; t < 4; ++t) {
            uint32_t af[4][4];
#pragma unroll
            for (int mi = 0; mi < 4; ++mi) {
                const int arow = wm * 64 + mi * 16 + (lane & 15);
                const int kb = t * 32 + ((lane >> 4) << 4);
                ldsm4(af[mi], sb + arow * 128 + (kb ^ ((arow & 7) << 4)));
            }
            uint32_t bf[16];
#pragma unroll
            for (int bi = 0; bi < 4; ++bi) {
                const int brow = wn * 64 + bi * 16 + ((lane >> 4) << 3) + (lane & 7);
                const int kb = t * 32 + (((lane >> 3) & 1) << 4);
                ldsm4(&bf[bi * 4], sb + APLANE + brow * 128 + (kb ^ ((brow & 7) << 4)));
            }
#pragma unroll
            for (int mi = 0; mi < 4; ++mi)
#pragma unroll
                for (int ni = 0; ni < 8; ++ni)
                    mma_f16(acc[mi][ni], af[mi], &bf[ni * 2]);
        }
    }

#pragma unroll
    for (int mi = 0; mi < 4; ++mi) {
#pragma unroll
        for (int ni = 0; ni < 8; ++ni) {
            const int col = colBase + wn * 64 + ni * 8 + tig * 2;
#pragma unroll
            for (int hf = 0; hf < 2; ++hf) {
                const int row = rowBase + wm * 64 + mi * 16 + gid + hf * 8;
                if (EPI == 0) {
                    const float2 bb = *reinterpret_cast<const float2*>(bias + col);
                    const float v0 = tanh_fast(acc[mi][ni][hf * 2 + 0] + bb.x);
                    const float v1 = tanh_fast(acc[mi][ni][hf * 2 + 1] + bb.y);
                    *reinterpret_cast<__half2*>(H + (size_t)row * HID + col) =
                        __floats2half2_rn(v0, v1);
                } else {
                    float2 v;
                    v.x = acc[mi][ni][hf * 2 + 0];
                    v.y = acc[mi][ni][hf * 2 + 1];
                    *reinterpret_cast<float2*>(P + (size_t)row * DIM + col) = v;
                }
            }
        }
    }
}

// GEMM1: H = tanh(Y @ W1^T + b1); grid (32, 8)
__global__ void __launch_bounds__(128, 2)
hgemm1(const __half* __restrict__ A, const __half* __restrict__ B,
       const float* __restrict__ bias, __half* __restrict__ H) {
    extern __shared__ char smem[];
    gemm_body<0>(A, B, bias, H, nullptr, 1024, 0, 16, smem);
}

// GEMM2 (split-K x4): P[z] = H @ W2^T slice; grid (8, 8, 4)
__global__ void __launch_bounds__(128, 2)
hgemm2(const __half* __restrict__ A, const __half* __restrict__ B,
       float* __restrict__ P) {
    extern __shared__ char smem[];
    gemm_body<1>(A, B, nullptr, nullptr, P + (size_t)blockIdx.z * BD, 4096,
                 (size_t)blockIdx.z * 2048, 16, smem);
}

// -------- reduce + RK4 stage update (fp32 master state chain) --------
template <int EPI>
__global__ void kreduce(const float* __restrict__ P, const float* __restrict__ b2,
                        const float* __restrict__ ybase, float* __restrict__ Yacc,
                        float* __restrict__ yout, __half* __restrict__ Yh,
                        const float* __restrict__ tspan, int step) {
    const int idx = blockIdx.x * 256 + threadIdx.x;
    const size_t i4 = (size_t)idx * 4;
    const float h = tspan[step + 1] - tspan[step];
    float4 k = *reinterpret_cast<const float4*>(P + i4);
    const float4 k1 = *reinterpret_cast<const float4*>(P + BD + i4);
    const float4 k2 = *reinterpret_cast<const float4*>(P + 2 * (size_t)BD + i4);
    const float4 k3 = *reinterpret_cast<const float4*>(P + 3 * (size_t)BD + i4);
    const float4 bb = *reinterpret_cast<const float4*>(b2 + (i4 & 1023));
    k.x += k1.x + k2.x + k3.x + bb.x;
    k.y += k1.y + k2.y + k3.y + bb.y;
    k.z += k1.z + k2.z + k3.z + bb.z;
    k.w += k1.w + k2.w + k3.w + bb.w;

    float4 o;
    if (EPI == 4) {
        const float4 aa = *reinterpret_cast<const float4*>(Yacc + i4);
        o.x = fmaf(h * (1.f / 6.f), k.x, aa.x);
        o.y = fmaf(h * (1.f / 6.f), k.y, aa.y);
        o.z = fmaf(h * (1.f / 6.f), k.z, aa.z);
        o.w = fmaf(h * (1.f / 6.f), k.w, aa.w);
        *reinterpret_cast<float4*>(yout + i4) = o;
    } else {
        const float4 yy = *reinterpret_cast<const float4*>(ybase + i4);
        const float cy = (EPI == 3) ? 1.0f : 0.5f;
        o.x = fmaf(cy * h, k.x, yy.x);
        o.y = fmaf(cy * h, k.y, yy.y);
        o.z = fmaf(cy * h, k.z, yy.z);
        o.w = fmaf(cy * h, k.w, yy.w);
        float4 aa;
        if (EPI == 1) {
            aa.x = fmaf(h * (1.f / 6.f), k.x, yy.x);
            aa.y = fmaf(h * (1.f / 6.f), k.y, yy.y);
            aa.z = fmaf(h * (1.f / 6.f), k.z, yy.z);
            aa.w = fmaf(h * (1.f / 6.f), k.w, yy.w);
        } else {
            aa = *reinterpret_cast<const float4*>(Yacc + i4);
            aa.x = fmaf(h * (1.f / 3.f), k.x, aa.x);
            aa.y = fmaf(h * (1.f / 3.f), k.y, aa.y);
            aa.z = fmaf(h * (1.f / 3.f), k.z, aa.z);
            aa.w = fmaf(h * (1.f / 3.f), k.w, aa.w);
        }
        *reinterpret_cast<float4*>(Yacc + i4) = aa;
    }
    uint2 hp;
    hp.x = h2_bits(__floats2half2_rn(o.x, o.y));
    hp.y = h2_bits(__floats2half2_rn(o.z, o.w));
    *reinterpret_cast<uint2*>(Yh + i4) = hp;
}

// fp32 [R,C] -> fp16 plane [C,R] (transpose + round)
__global__ void ktrans_h(const float* __restrict__ in, __half* __restrict__ oh,
                         int R, int C) {
    __shared__ float t[32][33];
    const int bx = blockIdx.x * 32;
    const int by = blockIdx.y * 32;
    for (int i = threadIdx.y; i < 32; i += 8)
        t[i][threadIdx.x] = in[(size_t)(by + i) * C + bx + threadIdx.x];
    __syncthreads();
    for (int i = threadIdx.y; i < 32; i += 8)
        oh[(size_t)(bx + i) * R + by + threadIdx.x] = __float2half(t[threadIdx.x][i]);
}

__global__ void ky(const float* __restrict__ in, __half* __restrict__ oh, int n) {
    int i = blockIdx.x * 256 + threadIdx.x;
    if (i < n) oh[i] = __float2half(in[i]);
}

extern "C" void kernel_launch(void* const* d_in, const int* in_sizes, int n_in,
                              void* d_out, int out_size) {
    const float* y_init = (const float*)d_in[0];
    const float* tspan = (const float*)d_in[1];
    const float* W1 = (const float*)d_in[2];
    const float* b1 = (const float*)d_in[3];
    const float* W2 = (const float*)d_in[4];
    const float* b2 = (const float*)d_in[5];
    float* out = (float*)d_out;

    __half *W1p, *W2p, *H, *Yh;
    float *Yacc, *P;
    cudaGetSymbolAddress((void**)&W1p, g_W1);
    cudaGetSymbolAddress((void**)&W2p, g_W2);
    cudaGetSymbolAddress((void**)&H, g_H);
    cudaGetSymbolAddress((void**)&Yh, g_Yh);
    cudaGetSymbolAddress((void**)&Yacc, g_Yacc);
    cudaGetSymbolAddress((void**)&P, g_P);

    const int SMEM = 3 * 2 * 128 * 128;  // 3 stages x 32 KB = 98304
    cudaFuncSetAttribute(hgemm1, cudaFuncAttributeMaxDynamicSharedMemorySize, SMEM);
    cudaFuncSetAttribute(hgemm2, cudaFuncAttributeMaxDynamicSharedMemorySize, SMEM);

    cudaMemcpyAsync(out, tspan, TSTEPS * sizeof(float), cudaMemcpyDeviceToDevice, 0);
    float* traj = out + TSTEPS;
    cudaMemcpyAsync(traj, y_init, (size_t)BD * sizeof(float), cudaMemcpyDeviceToDevice, 0);

    ktrans_h<<<dim3(HID / 32, DIM / 32), dim3(32, 8)>>>(W1, W1p, DIM, HID);
    ktrans_h<<<dim3(DIM / 32, HID / 32), dim3(32, 8)>>>(W2, W2p, HID, DIM);
    ky<<<BD / 256, 256>>>(y_init, Yh, BD);

    const dim3 g1(HID / 128, BATCH / 128);      // (32, 8) = 256 CTAs
    const dim3 g2(DIM / 128, BATCH / 128, 4);   // (8, 8, 4) = 256 CTAs

    for (int s = 0; s < TSTEPS - 1; ++s) {
        const float* y = traj + (size_t)s * BD;
        float* ynext = traj + (size_t)(s + 1) * BD;

        hgemm1<<<g1, 128, SMEM>>>(Yh, W1p, b1, H);
        hgemm2<<<g2, 128, SMEM>>>(H, W2p, P);
        kreduce<1><<<BD / 1024, 256>>>(P, b2, y, Yacc, nullptr, Yh, tspan, s);

        hgemm1<<<g1, 128, SMEM>>>(Yh, W1p, b1, H);
        hgemm2<<<g2, 128, SMEM>>>(H, W2p, P);
        kreduce<2><<<BD / 1024, 256>>>(P, b2, y, Yacc, nullptr, Yh, tspan, s);

        hgemm1<<<g1, 128, SMEM>>>(Yh, W1p, b1, H);
        hgemm2<<<g2, 128, SMEM>>>(H, W2p, P);
        kreduce<3><<<BD / 1024, 256>>>(P, b2, y, Yacc, nullptr, Yh, tspan, s);

        hgemm1<<<g1, 128, SMEM>>>(Yh, W1p, b1, H);
        hgemm2<<<g2, 128, SMEM>>>(H, W2p, P);
        kreduce<4><<<BD / 1024, 256>>>(P, b2, y, Yacc, ynext, Yh, tspan, s);
    }
}